// round 3
// baseline (speedup 1.0000x reference)
#include <cuda_runtime.h>
#include <math.h>

#define TPB 576
#define SMEM_BYTES 156288   // 37776 floats + 1296 ints

__device__ __forceinline__ float gelu_exact(float x) {
    return 0.5f * x * (1.0f + erff(x * 0.70710678118654752440f));
}

__global__ void __launch_bounds__(TPB, 1) gcn_kernel(
    const float* __restrict__ gin,  const float* __restrict__ gpos, const float* __restrict__ grel,
    const float* __restrict__ gW1,  const float* __restrict__ gb1,
    const float* __restrict__ gWc,  const float* __restrict__ gbc,
    const float* __restrict__ gW2,  const float* __restrict__ gb2,
    const float* __restrict__ gF1,  const float* __restrict__ gfb1,
    const float* __restrict__ gF2,  const float* __restrict__ gfb2,
    float* __restrict__ gout)
{
    extern __shared__ float sm[];
    float* sW1 = sm;                  // 1024  (32x32)
    float* sWc = sW1 + 1024;          // 4096  (64x64)
    float* sW2 = sWc + 4096;          // 2048  (32x64)
    float* sF1 = sW2 + 2048;          // 1024
    float* sF2 = sF1 + 1024;          // 1024
    float* sB  = sF2 + 1024;          // 192: [0,32) b1 [32,96) bc [96,128) b2 [128,160) fb1 [160,192) fb2
    float* sT  = sB + 192;            // 4608  tmp = in+pos, [c][n] stride 144
    float* sS  = sT + 4608;           // 9216  stacked [2C][n]: row 2c=xf_c, 2c+1=m_c
    float* sH  = sS + 9216;           // 9216  conv out [64][n]; also topk merge scratch
    float* sXn = sH + 9216;           // 5184  normalized nodes [n][c], stride 36 (16B aligned rows)
    float* sSq = sXn + 5184;          // 144
    int*   sIdx = (int*)(sSq + 144);  // 144*9

    const int tid = threadIdx.x;
    const int b   = blockIdx.x;

    // ---------------- load weights / biases / input ----------------
    for (int i = tid; i < 256;  i += TPB) ((float4*)sW1)[i] = ((const float4*)gW1)[i];
    for (int i = tid; i < 1024; i += TPB) ((float4*)sWc)[i] = ((const float4*)gWc)[i];
    for (int i = tid; i < 512;  i += TPB) ((float4*)sW2)[i] = ((const float4*)gW2)[i];
    for (int i = tid; i < 256;  i += TPB) ((float4*)sF1)[i] = ((const float4*)gF1)[i];
    for (int i = tid; i < 256;  i += TPB) ((float4*)sF2)[i] = ((const float4*)gF2)[i];
    if (tid < 32)       sB[tid] = gb1[tid];
    else if (tid < 96)  sB[tid] = gbc[tid - 32];
    else if (tid < 128) sB[tid] = gb2[tid - 96];
    else if (tid < 160) sB[tid] = gfb1[tid - 128];
    else if (tid < 192) sB[tid] = gfb2[tid - 160];
    {
        const float4* gi4 = (const float4*)(gin + (size_t)b * 4608);
        const float4* gp4 = (const float4*)gpos;
        for (int i = tid; i < 1152; i += TPB) {
            float4 a = gi4[i], p = gp4[i];
            a.x += p.x; a.y += p.y; a.z += p.z; a.w += p.w;
            ((float4*)sT)[i] = a;
        }
    }
    __syncthreads();

    // ---------------- fc1: xf = W1 @ tmp + b1 -> sS even rows ----------------
    {
        int q = tid / 36, r = tid - q * 36;      // 16 o-pairs x 36 n-quads = 576 tiles
        int o0 = q << 1, n0 = r << 2;
        float4 a0 = make_float4(0.f,0.f,0.f,0.f);
        float4 a1 = make_float4(0.f,0.f,0.f,0.f);
        const float* w0p = &sW1[o0 * 32];
        const float* w1p = w0p + 32;
        #pragma unroll
        for (int c = 0; c < 32; c++) {
            float w0 = w0p[c], w1 = w1p[c];
            float4 v = *(const float4*)&sT[c * 144 + n0];
            a0.x = fmaf(w0, v.x, a0.x); a0.y = fmaf(w0, v.y, a0.y);
            a0.z = fmaf(w0, v.z, a0.z); a0.w = fmaf(w0, v.w, a0.w);
            a1.x = fmaf(w1, v.x, a1.x); a1.y = fmaf(w1, v.y, a1.y);
            a1.z = fmaf(w1, v.z, a1.z); a1.w = fmaf(w1, v.w, a1.w);
        }
        float bb0 = sB[o0], bb1 = sB[o0 + 1];
        a0.x += bb0; a0.y += bb0; a0.z += bb0; a0.w += bb0;
        a1.x += bb1; a1.y += bb1; a1.z += bb1; a1.w += bb1;
        *(float4*)&sS[(2 * o0) * 144 + n0]     = a0;
        *(float4*)&sS[(2 * o0 + 2) * 144 + n0] = a1;
    }
    __syncthreads();

    // ---------------- normalize nodes -> sXn [n][c] (stride 36), sSq ----------------
    if (tid < 144) {
        float v[32]; float s = 0.f;
        #pragma unroll
        for (int c = 0; c < 32; c++) { float x = sS[(2 * c) * 144 + tid]; v[c] = x; s = fmaf(x, x, s); }
        float nrm = fmaxf(sqrtf(s), 1e-12f);
        float sq = 0.f;
        #pragma unroll
        for (int c = 0; c < 32; c++) { float xn = v[c] / nrm; sXn[tid * 36 + c] = xn; sq = fmaf(xn, xn, sq); }
        sSq[tid] = sq;
    }
    __syncthreads();

    // ---------------- pairwise dist + top-9 (4-way split of m per row) ----------------
    {
        const int row  = tid % 144;
        const int part = tid / 144;          // 0..3, each covers 36 m
        float v[32];
        #pragma unroll
        for (int c = 0; c < 32; c++) v[c] = sXn[row * 36 + c];
        const float sqn = sSq[row];
        float bd[9]; int bi[9];
        #pragma unroll
        for (int k = 0; k < 9; k++) { bd[k] = 3.0e38f; bi[k] = 0; }
        const int m0 = part * 36;
        for (int mm = 0; mm < 36; mm++) {
            const int m = m0 + mm;
            float relv = grel[m * 144 + row];   // relative_pos is symmetric; coalesced read
            const float4* xm = (const float4*)&sXn[m * 36];
            float d0 = 0.f, d1 = 0.f, d2 = 0.f, d3 = 0.f;
            #pragma unroll
            for (int c4 = 0; c4 < 8; c4++) {
                float4 a = xm[c4];
                d0 = fmaf(v[4*c4+0], a.x, d0);
                d1 = fmaf(v[4*c4+1], a.y, d1);
                d2 = fmaf(v[4*c4+2], a.z, d2);
                d3 = fmaf(v[4*c4+3], a.w, d3);
            }
            float dot = (d0 + d1) + (d2 + d3);
            float d = (sqn - 2.0f * dot) + sSq[m] + relv;
            if (d < bd[8]) {                     // strict-less: ties keep lower index (lax.top_k)
                bd[8] = d; bi[8] = m;
                #pragma unroll
                for (int j = 8; j > 0; --j) {
                    if (bd[j] < bd[j-1]) {
                        float td = bd[j]; bd[j] = bd[j-1]; bd[j-1] = td;
                        int   ti = bi[j]; bi[j] = bi[j-1]; bi[j-1] = ti;
                    }
                }
            }
        }
        // merge the 4 per-part lists (scratch in sH, which is free until conv)
        float* scrD = sH;
        int*   scrI = ((int*)sH) + 4096;
        if (part > 0) {
            int base = ((part - 1) * 144 + row) * 9;
            #pragma unroll
            for (int k = 0; k < 9; k++) { scrD[base + k] = bd[k]; scrI[base + k] = bi[k]; }
        }
        __syncthreads();
        if (part == 0) {
            for (int p = 0; p < 3; p++) {       // ascending m-range order preserves tie rule
                int base = (p * 144 + row) * 9;
                #pragma unroll
                for (int k = 0; k < 9; k++) {
                    float d = scrD[base + k]; int mi = scrI[base + k];
                    if (d < bd[8]) {
                        bd[8] = d; bi[8] = mi;
                        #pragma unroll
                        for (int j = 8; j > 0; --j) {
                            if (bd[j] < bd[j-1]) {
                                float td = bd[j]; bd[j] = bd[j-1]; bd[j-1] = td;
                                int   ti = bi[j]; bi[j] = bi[j-1]; bi[j-1] = ti;
                            }
                        }
                    }
                }
            }
            #pragma unroll
            for (int k = 0; k < 9; k++) sIdx[row * 9 + k] = bi[k];
        }
    }
    __syncthreads();

    // ---------------- MRConv: m_c[n] = max_k (xf[c][idx] - xf[c][n]) -> sS odd rows ----------------
    for (int task = tid; task < 4608; task += TPB) {
        int c = task / 144, n2 = task - c * 144;
        float xi = sS[(2 * c) * 144 + n2];
        float mx = -3.0e38f;
        #pragma unroll
        for (int k = 0; k < 9; k++) {
            int j = sIdx[n2 * 9 + k];
            mx = fmaxf(mx, sS[(2 * c) * 144 + j] - xi);
        }
        sS[(2 * c + 1) * 144 + n2] = mx;
    }
    __syncthreads();

    // ---------------- conv: hc = gelu(Wc @ stacked + bc) -> sH ----------------
    for (int tile = tid; tile < 1152; tile += TPB) {    // 32 o-pairs x 36 n-quads
        int q = tile / 36, r = tile - q * 36;
        int o0 = q << 1, n0 = r << 2;
        float4 a0 = make_float4(0.f,0.f,0.f,0.f);
        float4 a1 = make_float4(0.f,0.f,0.f,0.f);
        const float* w0p = &sWc[o0 * 64];
        const float* w1p = w0p + 64;
        #pragma unroll
        for (int c = 0; c < 64; c++) {
            float w0 = w0p[c], w1 = w1p[c];
            float4 v = *(const float4*)&sS[c * 144 + n0];
            a0.x = fmaf(w0, v.x, a0.x); a0.y = fmaf(w0, v.y, a0.y);
            a0.z = fmaf(w0, v.z, a0.z); a0.w = fmaf(w0, v.w, a0.w);
            a1.x = fmaf(w1, v.x, a1.x); a1.y = fmaf(w1, v.y, a1.y);
            a1.z = fmaf(w1, v.z, a1.z); a1.w = fmaf(w1, v.w, a1.w);
        }
        float bb0 = sB[32 + o0], bb1 = sB[32 + o0 + 1];
        a0.x = gelu_exact(a0.x + bb0); a0.y = gelu_exact(a0.y + bb0);
        a0.z = gelu_exact(a0.z + bb0); a0.w = gelu_exact(a0.w + bb0);
        a1.x = gelu_exact(a1.x + bb1); a1.y = gelu_exact(a1.y + bb1);
        a1.z = gelu_exact(a1.z + bb1); a1.w = gelu_exact(a1.w + bb1);
        *(float4*)&sH[o0 * 144 + n0]       = a0;
        *(float4*)&sH[(o0 + 1) * 144 + n0] = a1;
    }
    __syncthreads();

    // ---------------- fc2 + residual: x = W2 @ hc + b2 + tmp -> sT (in place) ----------------
    {
        int q = tid / 36, r = tid - q * 36;
        int o0 = q << 1, n0 = r << 2;
        float4 a0 = make_float4(0.f,0.f,0.f,0.f);
        float4 a1 = make_float4(0.f,0.f,0.f,0.f);
        const float* w0p = &sW2[o0 * 64];
        const float* w1p = w0p + 64;
        #pragma unroll
        for (int c = 0; c < 64; c++) {
            float w0 = w0p[c], w1 = w1p[c];
            float4 v = *(const float4*)&sH[c * 144 + n0];
            a0.x = fmaf(w0, v.x, a0.x); a0.y = fmaf(w0, v.y, a0.y);
            a0.z = fmaf(w0, v.z, a0.z); a0.w = fmaf(w0, v.w, a0.w);
            a1.x = fmaf(w1, v.x, a1.x); a1.y = fmaf(w1, v.y, a1.y);
            a1.z = fmaf(w1, v.z, a1.z); a1.w = fmaf(w1, v.w, a1.w);
        }
        float bb0 = sB[96 + o0], bb1 = sB[96 + o0 + 1];
        float4 t0 = *(float4*)&sT[o0 * 144 + n0];
        float4 t1 = *(float4*)&sT[(o0 + 1) * 144 + n0];
        a0.x += bb0 + t0.x; a0.y += bb0 + t0.y; a0.z += bb0 + t0.z; a0.w += bb0 + t0.w;
        a1.x += bb1 + t1.x; a1.y += bb1 + t1.y; a1.z += bb1 + t1.z; a1.w += bb1 + t1.w;
        *(float4*)&sT[o0 * 144 + n0]       = a0;   // each (o,n) owned by exactly this thread
        *(float4*)&sT[(o0 + 1) * 144 + n0] = a1;
    }
    __syncthreads();

    // ---------------- FFN fc1: h = gelu(F1 @ x + fb1) -> sS rows 0..31 ----------------
    {
        int q = tid / 36, r = tid - q * 36;
        int o0 = q << 1, n0 = r << 2;
        float4 a0 = make_float4(0.f,0.f,0.f,0.f);
        float4 a1 = make_float4(0.f,0.f,0.f,0.f);
        const float* w0p = &sF1[o0 * 32];
        const float* w1p = w0p + 32;
        #pragma unroll
        for (int c = 0; c < 32; c++) {
            float w0 = w0p[c], w1 = w1p[c];
            float4 v = *(const float4*)&sT[c * 144 + n0];
            a0.x = fmaf(w0, v.x, a0.x); a0.y = fmaf(w0, v.y, a0.y);
            a0.z = fmaf(w0, v.z, a0.z); a0.w = fmaf(w0, v.w, a0.w);
            a1.x = fmaf(w1, v.x, a1.x); a1.y = fmaf(w1, v.y, a1.y);
            a1.z = fmaf(w1, v.z, a1.z); a1.w = fmaf(w1, v.w, a1.w);
        }
        float bb0 = sB[128 + o0], bb1 = sB[128 + o0 + 1];
        a0.x = gelu_exact(a0.x + bb0); a0.y = gelu_exact(a0.y + bb0);
        a0.z = gelu_exact(a0.z + bb0); a0.w = gelu_exact(a0.w + bb0);
        a1.x = gelu_exact(a1.x + bb1); a1.y = gelu_exact(a1.y + bb1);
        a1.z = gelu_exact(a1.z + bb1); a1.w = gelu_exact(a1.w + bb1);
        *(float4*)&sS[o0 * 144 + n0]       = a0;
        *(float4*)&sS[(o0 + 1) * 144 + n0] = a1;
    }
    __syncthreads();

    // ---------------- FFN fc2 + residual -> global ----------------
    {
        int q = tid / 36, r = tid - q * 36;
        int o0 = q << 1, n0 = r << 2;
        float4 a0 = make_float4(0.f,0.f,0.f,0.f);
        float4 a1 = make_float4(0.f,0.f,0.f,0.f);
        const float* w0p = &sF2[o0 * 32];
        const float* w1p = w0p + 32;
        #pragma unroll
        for (int c = 0; c < 32; c++) {
            float w0 = w0p[c], w1 = w1p[c];
            float4 v = *(const float4*)&sS[c * 144 + n0];
            a0.x = fmaf(w0, v.x, a0.x); a0.y = fmaf(w0, v.y, a0.y);
            a0.z = fmaf(w0, v.z, a0.z); a0.w = fmaf(w0, v.w, a0.w);
            a1.x = fmaf(w1, v.x, a1.x); a1.y = fmaf(w1, v.y, a1.y);
            a1.z = fmaf(w1, v.z, a1.z); a1.w = fmaf(w1, v.w, a1.w);
        }
        float bb0 = sB[160 + o0], bb1 = sB[160 + o0 + 1];
        float4 t0 = *(float4*)&sT[o0 * 144 + n0];
        float4 t1 = *(float4*)&sT[(o0 + 1) * 144 + n0];
        a0.x += bb0 + t0.x; a0.y += bb0 + t0.y; a0.z += bb0 + t0.z; a0.w += bb0 + t0.w;
        a1.x += bb1 + t1.x; a1.y += bb1 + t1.y; a1.z += bb1 + t1.z; a1.w += bb1 + t1.w;
        float* go = gout + (size_t)b * 4608;
        *(float4*)&go[o0 * 144 + n0]       = a0;
        *(float4*)&go[(o0 + 1) * 144 + n0] = a1;
    }
}

extern "C" void kernel_launch(void* const* d_in, const int* in_sizes, int n_in,
                              void* d_out, int out_size) {
    (void)n_in;
    int B = in_sizes[0] / (32 * 144);
    cudaFuncSetAttribute(gcn_kernel, cudaFuncAttributeMaxDynamicSharedMemorySize, SMEM_BYTES);
    gcn_kernel<<<B, TPB, SMEM_BYTES>>>(
        (const float*)d_in[0],  (const float*)d_in[1],  (const float*)d_in[2],
        (const float*)d_in[3],  (const float*)d_in[4],
        (const float*)d_in[5],  (const float*)d_in[6],
        (const float*)d_in[7],  (const float*)d_in[8],
        (const float*)d_in[9],  (const float*)d_in[10],
        (const float*)d_in[11], (const float*)d_in[12],
        (float*)d_out);
}